// round 2
// baseline (speedup 1.0000x reference)
#include <cuda_runtime.h>
#include <cuda_bf16.h>
#include <math.h>

#define N_NODES 100000
#define N_EDGES 1600000
#define IN_C 64
#define HID_C 64
#define OUT_C 40

// Scratch (allocation-free rule: __device__ globals)
__device__ float g_tmp[(size_t)N_NODES * HID_C];   // GEMM output (pre-norm messages)
__device__ float g_h[(size_t)N_NODES * HID_C];     // aggregated layer output / next input
__device__ float g_dinv[N_NODES];
__device__ float g_norm[N_EDGES];                  // dinv[src]*dinv[dst], computed once
__device__ int   g_deg[N_NODES];

// ---------------------------------------------------------------------------
// packed f32x2 helpers (Blackwell)
// ---------------------------------------------------------------------------
__device__ __forceinline__ void fma2(unsigned long long& d, unsigned long long a,
                                     unsigned long long b) {
    asm("fma.rn.f32x2 %0, %1, %2, %0;" : "+l"(d) : "l"(a), "l"(b));
}
__device__ __forceinline__ unsigned long long pack2(float x) {
    unsigned long long p;
    asm("mov.b64 %0, {%1, %1};" : "=l"(p) : "f"(x));
    return p;
}
__device__ __forceinline__ void unpack2(unsigned long long p, float& lo, float& hi) {
    asm("mov.b64 {%0, %1}, %2;" : "=f"(lo), "=f"(hi) : "l"(p));
}

// ---------------------------------------------------------------------------
// degree / normalization
// ---------------------------------------------------------------------------
__global__ void zero_deg_kernel(int N) {
    int i = blockIdx.x * blockDim.x + threadIdx.x;
    if (i < N) g_deg[i] = 0;
}

__global__ void deg_kernel(const int* __restrict__ dst, int E) {
    int i = blockIdx.x * blockDim.x + threadIdx.x;
    if (i < E) atomicAdd(&g_deg[dst[i]], 1);
}

__global__ void dinv_kernel(int N) {
    int i = blockIdx.x * blockDim.x + threadIdx.x;
    if (i < N) g_dinv[i] = rsqrtf((float)(g_deg[i] + 1));  // +1 self loop; always > 0
}

__global__ void norm_kernel(const int* __restrict__ src, const int* __restrict__ dst, int E) {
    int i = blockIdx.x * blockDim.x + threadIdx.x;
    if (i < E) g_norm[i] = g_dinv[src[i]] * g_dinv[dst[i]];
}

// ---------------------------------------------------------------------------
// fused dense transform + self-loop/bias init:
//   y = (relu?)X[r,:] @ W ;  tmp[r,:] = y ;  h[r,:] = b + dinv[r]^2 * y
// block = 256 threads = 64 rows x 4 column-groups; f32x2 packed FMA
// ---------------------------------------------------------------------------
template <int IN, int OUT, bool RELU>
__global__ void gemm_fused_kernel(const float* __restrict__ X, const float* __restrict__ W,
                                  const float* __restrict__ b,
                                  float* __restrict__ tmp, float* __restrict__ h, int N) {
    constexpr int CPT = OUT / 4;        // cols per thread (16 or 10)
    constexpr int PAIRS = CPT / 2;      // f32x2 pairs (8 or 5)
    __shared__ __align__(16) float Ws[IN * OUT];
    __shared__ float bs[OUT];
    for (int i = threadIdx.x; i < IN * OUT; i += blockDim.x) Ws[i] = W[i];
    for (int i = threadIdx.x; i < OUT; i += blockDim.x) bs[i] = b[i];
    __syncthreads();

    int cg = threadIdx.x & 3;
    int r  = blockIdx.x * 64 + (threadIdx.x >> 2);
    if (r >= N) return;

    unsigned long long acc[PAIRS];
#pragma unroll
    for (int j = 0; j < PAIRS; j++) acc[j] = 0ull;

    const float4* xr = reinterpret_cast<const float4*>(X + (size_t)r * IN);
#pragma unroll
    for (int kc = 0; kc < IN / 16; kc++) {       // k in chunks of 16
        float xk[16];
#pragma unroll
        for (int q = 0; q < 4; q++) {
            float4 xv = xr[kc * 4 + q];
            if (RELU) {
                xv.x = fmaxf(xv.x, 0.f); xv.y = fmaxf(xv.y, 0.f);
                xv.z = fmaxf(xv.z, 0.f); xv.w = fmaxf(xv.w, 0.f);
            }
            xk[4 * q] = xv.x; xk[4 * q + 1] = xv.y; xk[4 * q + 2] = xv.z; xk[4 * q + 3] = xv.w;
        }
#pragma unroll
        for (int kk = 0; kk < 16; kk++) {
            int k = kc * 16 + kk;
            unsigned long long xx = pack2(xk[kk]);
            const unsigned long long* w2 =
                reinterpret_cast<const unsigned long long*>(Ws + k * OUT + cg * CPT);
#pragma unroll
            for (int j = 0; j < PAIRS; j++) fma2(acc[j], xx, w2[j]);
        }
    }

    float di = g_dinv[r];
    float s = di * di;
    float* trow = tmp + (size_t)r * OUT + cg * CPT;
    float* hrow = h   + (size_t)r * OUT + cg * CPT;
    const float* brow = bs + cg * CPT;
#pragma unroll
    for (int j = 0; j < PAIRS; j++) {
        float lo, hi;
        unpack2(acc[j], lo, hi);
        trow[2 * j]     = lo;
        trow[2 * j + 1] = hi;
        hrow[2 * j]     = brow[2 * j]     + lo * s;
        hrow[2 * j + 1] = brow[2 * j + 1] + hi * s;
    }
}

// ---------------------------------------------------------------------------
// edge scatter: out[dst,:] += tmp[src,:] * norm[e]
// C4 threads per edge, one float4 each; vector RED
// ---------------------------------------------------------------------------
__device__ __forceinline__ void red_add_v4(float* addr, float4 v) {
    asm volatile("red.global.add.v4.f32 [%0], {%1, %2, %3, %4};"
                 :: "l"(addr), "f"(v.x), "f"(v.y), "f"(v.z), "f"(v.w)
                 : "memory");
}

template <int C4>
__global__ void scatter_kernel(const int* __restrict__ src, const int* __restrict__ dst,
                               const float* __restrict__ tmp, float* __restrict__ out, int E) {
    int idx = blockIdx.x * blockDim.x + threadIdx.x;
    int e = idx / C4;
    int c4 = idx - e * C4;
    if (e >= E) return;
    int s = __ldg(src + e);
    int d = __ldg(dst + e);
    float nrm = __ldg(&g_norm[e]);
    float4 v = reinterpret_cast<const float4*>(tmp)[(size_t)s * C4 + c4];
    v.x *= nrm; v.y *= nrm; v.z *= nrm; v.w *= nrm;
    red_add_v4(reinterpret_cast<float*>(reinterpret_cast<float4*>(out) + (size_t)d * C4 + c4), v);
}

// ---------------------------------------------------------------------------
// row-wise log_softmax over OUT_C=40
// ---------------------------------------------------------------------------
__global__ void lsm_kernel(const float* __restrict__ h, float* __restrict__ out, int N) {
    int r = blockIdx.x * blockDim.x + threadIdx.x;
    if (r >= N) return;
    float v[OUT_C];
    const float4* hr = reinterpret_cast<const float4*>(h + (size_t)r * OUT_C);
#pragma unroll
    for (int j = 0; j < OUT_C / 4; j++) {
        float4 t = hr[j];
        v[4 * j] = t.x; v[4 * j + 1] = t.y; v[4 * j + 2] = t.z; v[4 * j + 3] = t.w;
    }
    float m = v[0];
#pragma unroll
    for (int j = 1; j < OUT_C; j++) m = fmaxf(m, v[j]);
    float s = 0.f;
#pragma unroll
    for (int j = 0; j < OUT_C; j++) s += __expf(v[j] - m);
    float l = m + logf(s);
    float4* orow = reinterpret_cast<float4*>(out + (size_t)r * OUT_C);
#pragma unroll
    for (int j = 0; j < OUT_C / 4; j++)
        orow[j] = make_float4(v[4 * j] - l, v[4 * j + 1] - l, v[4 * j + 2] - l, v[4 * j + 3] - l);
}

// ---------------------------------------------------------------------------
// launcher
// ---------------------------------------------------------------------------
extern "C" void kernel_launch(void* const* d_in, const int* in_sizes, int n_in,
                              void* d_out, int out_size) {
    const float* x  = (const float*)d_in[0];
    const int*   ei = (const int*)d_in[1];
    const float* W1 = (const float*)d_in[2];
    const float* b1 = (const float*)d_in[3];
    const float* Wh = (const float*)d_in[4];
    const float* bh = (const float*)d_in[5];
    const float* W2 = (const float*)d_in[6];
    const float* b2 = (const float*)d_in[7];
    float* out = (float*)d_out;

    int N = in_sizes[0] / IN_C;
    int E = in_sizes[1] / 2;
    const int* src = ei;
    const int* dst = ei + E;

    float *p_tmp, *p_h;
    cudaGetSymbolAddress((void**)&p_tmp, g_tmp);
    cudaGetSymbolAddress((void**)&p_h, g_h);

    const int T = 256;
    int nb_N = (N + T - 1) / T;
    int nb_E = (E + T - 1) / T;
    int nb_R = (N + 63) / 64;  // gemm blocks: 64 rows each

    // normalization: deg (with self loop) -> dinv -> per-edge norm
    zero_deg_kernel<<<nb_N, T>>>(N);
    deg_kernel<<<nb_E, T>>>(dst, E);
    dinv_kernel<<<nb_N, T>>>(N);
    norm_kernel<<<nb_E, T>>>(src, dst, E);

    // ---- layer 1 ----
    gemm_fused_kernel<IN_C, HID_C, false><<<nb_R, T>>>(x, W1, b1, p_tmp, p_h, N);
    scatter_kernel<HID_C / 4><<<((long long)E * (HID_C / 4) + T - 1) / T, T>>>(src, dst, p_tmp, p_h, E);

    // ---- layer 2 ----
    gemm_fused_kernel<HID_C, HID_C, true><<<nb_R, T>>>(p_h, Wh, bh, p_tmp, p_h, N);
    scatter_kernel<HID_C / 4><<<((long long)E * (HID_C / 4) + T - 1) / T, T>>>(src, dst, p_tmp, p_h, E);

    // ---- layer 3 (40-wide) ----
    gemm_fused_kernel<HID_C, OUT_C, true><<<nb_R, T>>>(p_h, W2, b2, p_tmp, p_h, N);
    scatter_kernel<OUT_C / 4><<<((long long)E * (OUT_C / 4) + T - 1) / T, T>>>(src, dst, p_tmp, p_h, E);

    lsm_kernel<<<nb_N, T>>>(p_h, out, N);
}

// round 3
// speedup vs baseline: 2.0386x; 2.0386x over previous
#include <cuda_runtime.h>
#include <cuda_bf16.h>
#include <math.h>

#define N_NODES 100000
#define N_EDGES 1600000
#define IN_C 64
#define HID_C 64
#define OUT_C 40
#define SCAN_BS 512
#define SCAN_NB ((N_NODES + SCAN_BS - 1) / SCAN_BS)   // 196

// Scratch (allocation-free rule: __device__ globals)
__device__ float g_tmp[(size_t)N_NODES * HID_C];   // GEMM output (pre-norm messages)
__device__ float g_h[(size_t)N_NODES * HID_C];     // aggregated layer output / next input
__device__ float g_dinv[N_NODES];
__device__ int   g_deg[N_NODES];
__device__ int   g_rowptr[N_NODES + 1];
__device__ int   g_cursor[N_NODES];
__device__ int   g_bsum[SCAN_NB];
__device__ int   g_boff[SCAN_NB];
__device__ int2  g_epair[N_EDGES];                 // {src, norm(bits)} binned by dst

// ---------------------------------------------------------------------------
// degree / normalization
// ---------------------------------------------------------------------------
__global__ void zero_deg_kernel(int N) {
    int i = blockIdx.x * blockDim.x + threadIdx.x;
    if (i < N) g_deg[i] = 0;
}

__global__ void deg_kernel(const int* __restrict__ dst, int E) {
    int i = blockIdx.x * blockDim.x + threadIdx.x;
    if (i < E) atomicAdd(&g_deg[dst[i]], 1);
}

__global__ void dinv_kernel(int N) {
    int i = blockIdx.x * blockDim.x + threadIdx.x;
    if (i < N) g_dinv[i] = rsqrtf((float)(g_deg[i] + 1));  // +1 self loop; always > 0
}

// ---------------------------------------------------------------------------
// CSR build: block-wise exclusive scan of deg -> rowptr, then bin edges
// ---------------------------------------------------------------------------
__global__ void scan_block_kernel(int N) {
    __shared__ int s[SCAN_BS];
    int i = blockIdx.x * SCAN_BS + threadIdx.x;
    int v = (i < N) ? g_deg[i] : 0;
    s[threadIdx.x] = v;
    __syncthreads();
#pragma unroll
    for (int off = 1; off < SCAN_BS; off <<= 1) {
        int t = 0;
        if (threadIdx.x >= off) t = s[threadIdx.x - off];
        __syncthreads();
        if (threadIdx.x >= off) s[threadIdx.x] += t;
        __syncthreads();
    }
    if (i < N) g_rowptr[i] = s[threadIdx.x] - v;       // exclusive, block-local
    if (threadIdx.x == SCAN_BS - 1) g_bsum[blockIdx.x] = s[SCAN_BS - 1];
}

__global__ void scan_bsum_kernel(int NB) {
    __shared__ int s[SCAN_BS];
    int v = (threadIdx.x < NB) ? g_bsum[threadIdx.x] : 0;
    s[threadIdx.x] = v;
    __syncthreads();
#pragma unroll
    for (int off = 1; off < SCAN_BS; off <<= 1) {
        int t = 0;
        if (threadIdx.x >= off) t = s[threadIdx.x - off];
        __syncthreads();
        if (threadIdx.x >= off) s[threadIdx.x] += t;
        __syncthreads();
    }
    if (threadIdx.x < NB) g_boff[threadIdx.x] = s[threadIdx.x] - v;  // exclusive
}

__global__ void add_off_kernel(int N, int E) {
    int i = blockIdx.x * blockDim.x + threadIdx.x;
    if (i < N) {
        int r = g_rowptr[i] + g_boff[i >> 9];
        g_rowptr[i] = r;
        g_cursor[i] = r;
    }
    if (i == 0) g_rowptr[N] = E;
}

__global__ void fill_kernel(const int* __restrict__ src, const int* __restrict__ dst, int E) {
    int e = blockIdx.x * blockDim.x + threadIdx.x;
    if (e >= E) return;
    int s = src[e], d = dst[e];
    float nrm = g_dinv[s] * g_dinv[d];
    int pos = atomicAdd(&g_cursor[d], 1);
    g_epair[pos] = make_int2(s, __float_as_int(nrm));
}

// ---------------------------------------------------------------------------
// dense transform (round-1 proven kernel): Y[r,:] = (relu?)X[r,:] @ W
// ---------------------------------------------------------------------------
template <int IN, int OUT, bool RELU>
__global__ void gemm_kernel(const float* __restrict__ X, const float* __restrict__ W,
                            float* __restrict__ Y, int N) {
    __shared__ float Ws[IN * OUT];
    for (int i = threadIdx.x; i < IN * OUT; i += blockDim.x) Ws[i] = W[i];
    __syncthreads();

    int r = blockIdx.x * blockDim.x + threadIdx.x;
    if (r >= N) return;

    float acc[OUT];
#pragma unroll
    for (int j = 0; j < OUT; j++) acc[j] = 0.f;

    const float4* xr = reinterpret_cast<const float4*>(X + (size_t)r * IN);
#pragma unroll 4
    for (int k4 = 0; k4 < IN / 4; k4++) {
        float4 xv = xr[k4];
        if (RELU) {
            xv.x = fmaxf(xv.x, 0.f); xv.y = fmaxf(xv.y, 0.f);
            xv.z = fmaxf(xv.z, 0.f); xv.w = fmaxf(xv.w, 0.f);
        }
        float xs[4] = {xv.x, xv.y, xv.z, xv.w};
#pragma unroll
        for (int kk = 0; kk < 4; kk++) {
            float x = xs[kk];
            const float4* wr = reinterpret_cast<const float4*>(Ws + (4 * k4 + kk) * OUT);
#pragma unroll
            for (int j = 0; j < OUT / 4; j++) {
                float4 w = wr[j];
                acc[4 * j + 0] += x * w.x;
                acc[4 * j + 1] += x * w.y;
                acc[4 * j + 2] += x * w.z;
                acc[4 * j + 3] += x * w.w;
            }
        }
    }
    float4* yr = reinterpret_cast<float4*>(Y + (size_t)r * OUT);
#pragma unroll
    for (int j = 0; j < OUT / 4; j++)
        yr[j] = make_float4(acc[4 * j], acc[4 * j + 1], acc[4 * j + 2], acc[4 * j + 3]);
}

// ---------------------------------------------------------------------------
// CSR aggregate (+ fused self-loop/bias init, optional fused log_softmax):
//   out[d,:] = b + dinv[d]^2 * tmp[d,:] + sum_{e in row d} norm[e] * tmp[src[e],:]
// 16 lanes per row, one float4 per lane (lanes >= C4 idle on a 40-wide layer)
// ---------------------------------------------------------------------------
template <int C4, bool LSM>
__global__ void aggregate_kernel(const float* __restrict__ tmp, const float* __restrict__ b,
                                 float* __restrict__ outp, int N) {
    int g    = blockIdx.x * 16 + (threadIdx.x >> 4);
    int lane = threadIdx.x & 15;
    bool rowok = (g < N);
    int row  = rowok ? g : 0;
    bool act = rowok && (lane < C4);

    const float4* t4 = reinterpret_cast<const float4*>(tmp);
    const float4* b4 = reinterpret_cast<const float4*>(b);

    float4 acc = make_float4(0.f, 0.f, 0.f, 0.f);
    int beg = 0, end = 0;
    if (rowok) {
        beg = g_rowptr[row];
        end = g_rowptr[row + 1];
    }
    if (act) {
        float di = g_dinv[row];
        float s2 = di * di;
        float4 t = t4[(size_t)row * C4 + lane];
        float4 bb = b4[lane];
        acc.x = bb.x + s2 * t.x; acc.y = bb.y + s2 * t.y;
        acc.z = bb.z + s2 * t.z; acc.w = bb.w + s2 * t.w;
    }

    int j = beg;
    for (; j + 1 < end; j += 2) {                       // 2-way unroll for MLP
        int2 p0 = __ldg(&g_epair[j]);
        int2 p1 = __ldg(&g_epair[j + 1]);
        if (act) {
            float4 v0 = __ldg(&t4[(size_t)p0.x * C4 + lane]);
            float4 v1 = __ldg(&t4[(size_t)p1.x * C4 + lane]);
            float n0 = __int_as_float(p0.y), n1 = __int_as_float(p1.y);
            acc.x += n0 * v0.x + n1 * v1.x;
            acc.y += n0 * v0.y + n1 * v1.y;
            acc.z += n0 * v0.z + n1 * v1.z;
            acc.w += n0 * v0.w + n1 * v1.w;
        }
    }
    if (j < end) {
        int2 p0 = __ldg(&g_epair[j]);
        if (act) {
            float4 v0 = __ldg(&t4[(size_t)p0.x * C4 + lane]);
            float n0 = __int_as_float(p0.y);
            acc.x += n0 * v0.x; acc.y += n0 * v0.y;
            acc.z += n0 * v0.z; acc.w += n0 * v0.w;
        }
    }

    if (LSM) {
        // row-wise log_softmax across the 16-lane group (width-16 butterfly)
        float m = act ? fmaxf(fmaxf(acc.x, acc.y), fmaxf(acc.z, acc.w)) : -INFINITY;
#pragma unroll
        for (int k = 8; k >= 1; k >>= 1)
            m = fmaxf(m, __shfl_xor_sync(0xffffffffu, m, k, 16));
        float s = act ? (__expf(acc.x - m) + __expf(acc.y - m) +
                         __expf(acc.z - m) + __expf(acc.w - m)) : 0.f;
#pragma unroll
        for (int k = 8; k >= 1; k >>= 1)
            s += __shfl_xor_sync(0xffffffffu, s, k, 16);
        float l = m + logf(s);
        if (act) {
            reinterpret_cast<float4*>(outp)[(size_t)row * C4 + lane] =
                make_float4(acc.x - l, acc.y - l, acc.z - l, acc.w - l);
        }
    } else if (act) {
        reinterpret_cast<float4*>(outp)[(size_t)row * C4 + lane] = acc;
    }
}

// ---------------------------------------------------------------------------
// launcher
// ---------------------------------------------------------------------------
extern "C" void kernel_launch(void* const* d_in, const int* in_sizes, int n_in,
                              void* d_out, int out_size) {
    const float* x  = (const float*)d_in[0];
    const int*   ei = (const int*)d_in[1];
    const float* W1 = (const float*)d_in[2];
    const float* b1 = (const float*)d_in[3];
    const float* Wh = (const float*)d_in[4];
    const float* bh = (const float*)d_in[5];
    const float* W2 = (const float*)d_in[6];
    const float* b2 = (const float*)d_in[7];
    float* out = (float*)d_out;

    int N = in_sizes[0] / IN_C;
    int E = in_sizes[1] / 2;
    const int* src = ei;
    const int* dst = ei + E;

    float *p_tmp, *p_h;
    cudaGetSymbolAddress((void**)&p_tmp, g_tmp);
    cudaGetSymbolAddress((void**)&p_h, g_h);

    const int T = 256;
    int nb_N = (N + T - 1) / T;
    int nb_E = (E + T - 1) / T;
    int nb_A = (N + 15) / 16;   // aggregate: 16 rows/block

    // ---- normalization + CSR build ----
    zero_deg_kernel<<<nb_N, T>>>(N);
    deg_kernel<<<nb_E, T>>>(dst, E);
    dinv_kernel<<<nb_N, T>>>(N);
    scan_block_kernel<<<SCAN_NB, SCAN_BS>>>(N);
    scan_bsum_kernel<<<1, SCAN_BS>>>(SCAN_NB);
    add_off_kernel<<<nb_N, T>>>(N, E);
    fill_kernel<<<nb_E, T>>>(src, dst, E);

    // ---- layer 1 ----
    gemm_kernel<IN_C, HID_C, false><<<nb_N, T>>>(x, W1, p_tmp, N);
    aggregate_kernel<HID_C / 4, false><<<nb_A, T>>>(p_tmp, b1, p_h, N);

    // ---- layer 2 ----
    gemm_kernel<HID_C, HID_C, true><<<nb_N, T>>>(p_h, Wh, p_tmp, N);
    aggregate_kernel<HID_C / 4, false><<<nb_A, T>>>(p_tmp, bh, p_h, N);

    // ---- layer 3 (40-wide) + fused log_softmax ----
    gemm_kernel<HID_C, OUT_C, true><<<nb_N, T>>>(p_h, W2, p_tmp, N);
    aggregate_kernel<OUT_C / 4, true><<<nb_A, T>>>(p_tmp, b2, out, N);
}

// round 4
// speedup vs baseline: 2.1673x; 1.0631x over previous
#include <cuda_runtime.h>
#include <cuda_bf16.h>
#include <math.h>

#define N_NODES 100000
#define N_EDGES 1600000
#define IN_C 64
#define HID_C 64
#define OUT_C 40
#define SCAN_BS 512
#define SCAN_NB ((N_NODES + SCAN_BS - 1) / SCAN_BS)   // 196

// Scratch (allocation-free rule: __device__ globals)
__device__ float g_tmp[(size_t)N_NODES * HID_C];   // GEMM output (pre-norm messages)
__device__ float g_h[(size_t)N_NODES * HID_C];     // aggregated layer output / next input
__device__ float g_dinv[N_NODES];
__device__ int   g_deg[N_NODES];
__device__ int   g_rowptr[N_NODES + 1];
__device__ int   g_cursor[N_NODES];
__device__ int   g_bsum[SCAN_NB];
__device__ int   g_boff[SCAN_NB];
__device__ int2  g_epair[N_EDGES];                 // {src, norm(bits)} binned by dst

// ---------------------------------------------------------------------------
// degree
// ---------------------------------------------------------------------------
__global__ void zero_deg_kernel(int N) {
    int i = blockIdx.x * blockDim.x + threadIdx.x;
    if (i < N) g_deg[i] = 0;
}

__global__ void deg_kernel(const int* __restrict__ dst, int E) {
    int i = blockIdx.x * blockDim.x + threadIdx.x;
    if (i < E) atomicAdd(&g_deg[dst[i]], 1);
}

// ---------------------------------------------------------------------------
// CSR build: block-wise exclusive scan of deg -> rowptr (dinv fused here)
// ---------------------------------------------------------------------------
__global__ void scan_block_kernel(int N) {
    __shared__ int s[SCAN_BS];
    int i = blockIdx.x * SCAN_BS + threadIdx.x;
    int v = (i < N) ? g_deg[i] : 0;
    if (i < N) g_dinv[i] = rsqrtf((float)(v + 1));     // +1 self loop; always > 0
    s[threadIdx.x] = v;
    __syncthreads();
#pragma unroll
    for (int off = 1; off < SCAN_BS; off <<= 1) {
        int t = 0;
        if (threadIdx.x >= off) t = s[threadIdx.x - off];
        __syncthreads();
        if (threadIdx.x >= off) s[threadIdx.x] += t;
        __syncthreads();
    }
    if (i < N) g_rowptr[i] = s[threadIdx.x] - v;       // exclusive, block-local
    if (threadIdx.x == SCAN_BS - 1) g_bsum[blockIdx.x] = s[SCAN_BS - 1];
}

__global__ void scan_bsum_kernel(int NB) {
    __shared__ int s[SCAN_BS];
    int v = (threadIdx.x < NB) ? g_bsum[threadIdx.x] : 0;
    s[threadIdx.x] = v;
    __syncthreads();
#pragma unroll
    for (int off = 1; off < SCAN_BS; off <<= 1) {
        int t = 0;
        if (threadIdx.x >= off) t = s[threadIdx.x - off];
        __syncthreads();
        if (threadIdx.x >= off) s[threadIdx.x] += t;
        __syncthreads();
    }
    if (threadIdx.x < NB) g_boff[threadIdx.x] = s[threadIdx.x] - v;  // exclusive
}

__global__ void add_off_kernel(int N, int E) {
    int i = blockIdx.x * blockDim.x + threadIdx.x;
    if (i < N) {
        int r = g_rowptr[i] + g_boff[i >> 9];
        g_rowptr[i] = r;
        g_cursor[i] = r;
    }
    if (i == 0) g_rowptr[N] = E;
}

__global__ void fill_kernel(const int* __restrict__ src, const int* __restrict__ dst, int E) {
    int e = blockIdx.x * blockDim.x + threadIdx.x;
    if (e >= E) return;
    int s = src[e], d = dst[e];
    float nrm = g_dinv[s] * g_dinv[d];
    int pos = atomicAdd(&g_cursor[d], 1);
    g_epair[pos] = make_int2(s, __float_as_int(nrm));
}

// ---------------------------------------------------------------------------
// dense transform v2: Y[r,:] = (relu?)X[r,:] @ W
// 2 threads per row, interleaved float4 column chunks (NJ = OUT/8 each)
// ~50 regs -> high occupancy (vs 128-reg/21%-occ v1)
// ---------------------------------------------------------------------------
template <int IN, int OUT, bool RELU>
__global__ void __launch_bounds__(256) gemm_kernel(const float* __restrict__ X,
                                                   const float* __restrict__ W,
                                                   float* __restrict__ Y, int N) {
    constexpr int NJ = OUT / 8;   // float4 chunks per thread (8 for 64, 5 for 40)
    __shared__ __align__(16) float Ws[IN * OUT];
    for (int i = threadIdx.x; i < IN * OUT; i += blockDim.x) Ws[i] = W[i];
    __syncthreads();

    int half = threadIdx.x & 1;
    int r = blockIdx.x * 128 + (threadIdx.x >> 1);
    if (r >= N) return;

    float4 acc[NJ];
#pragma unroll
    for (int j = 0; j < NJ; j++) acc[j] = make_float4(0.f, 0.f, 0.f, 0.f);

    const float4* xr = reinterpret_cast<const float4*>(X + (size_t)r * IN);
#pragma unroll 4
    for (int k4 = 0; k4 < IN / 4; k4++) {
        float4 xv = xr[k4];
        if (RELU) {
            xv.x = fmaxf(xv.x, 0.f); xv.y = fmaxf(xv.y, 0.f);
            xv.z = fmaxf(xv.z, 0.f); xv.w = fmaxf(xv.w, 0.f);
        }
        float xs[4] = {xv.x, xv.y, xv.z, xv.w};
#pragma unroll
        for (int kk = 0; kk < 4; kk++) {
            float x = xs[kk];
            const float4* wr = reinterpret_cast<const float4*>(Ws + (4 * k4 + kk) * OUT);
#pragma unroll
            for (int j = 0; j < NJ; j++) {
                float4 w = wr[2 * j + half];
                acc[j].x += x * w.x; acc[j].y += x * w.y;
                acc[j].z += x * w.z; acc[j].w += x * w.w;
            }
        }
    }
    float4* yr = reinterpret_cast<float4*>(Y + (size_t)r * OUT);
#pragma unroll
    for (int j = 0; j < NJ; j++) yr[2 * j + half] = acc[j];
}

// ---------------------------------------------------------------------------
// CSR aggregate (+ fused self-loop/bias init, optional fused log_softmax):
//   out[d,:] = b + dinv[d]^2 * tmp[d,:] + sum_{e in row d} norm[e] * tmp[src[e],:]
// 16 lanes per row, one float4 per lane; 4-way edge unroll for MLP
// ---------------------------------------------------------------------------
template <int C4, bool LSM>
__global__ void aggregate_kernel(const float* __restrict__ tmp, const float* __restrict__ b,
                                 float* __restrict__ outp, int N) {
    int g    = blockIdx.x * 16 + (threadIdx.x >> 4);
    int lane = threadIdx.x & 15;
    bool rowok = (g < N);
    int row  = rowok ? g : 0;
    bool act = rowok && (lane < C4);

    const float4* t4 = reinterpret_cast<const float4*>(tmp);
    const float4* b4 = reinterpret_cast<const float4*>(b);

    float4 acc = make_float4(0.f, 0.f, 0.f, 0.f);
    int beg = 0, end = 0;
    if (rowok) {
        beg = g_rowptr[row];
        end = g_rowptr[row + 1];
    }
    if (act) {
        float di = g_dinv[row];
        float s2 = di * di;
        float4 t = t4[(size_t)row * C4 + lane];
        float4 bb = b4[lane];
        acc.x = bb.x + s2 * t.x; acc.y = bb.y + s2 * t.y;
        acc.z = bb.z + s2 * t.z; acc.w = bb.w + s2 * t.w;
    }

    int j = beg;
    for (; j + 3 < end; j += 4) {                       // 4-way unroll for MLP
        int2 p0 = __ldg(&g_epair[j]);
        int2 p1 = __ldg(&g_epair[j + 1]);
        int2 p2 = __ldg(&g_epair[j + 2]);
        int2 p3 = __ldg(&g_epair[j + 3]);
        if (act) {
            float4 v0 = __ldg(&t4[(size_t)p0.x * C4 + lane]);
            float4 v1 = __ldg(&t4[(size_t)p1.x * C4 + lane]);
            float4 v2 = __ldg(&t4[(size_t)p2.x * C4 + lane]);
            float4 v3 = __ldg(&t4[(size_t)p3.x * C4 + lane]);
            float n0 = __int_as_float(p0.y), n1 = __int_as_float(p1.y);
            float n2 = __int_as_float(p2.y), n3 = __int_as_float(p3.y);
            acc.x += n0 * v0.x + n1 * v1.x + n2 * v2.x + n3 * v3.x;
            acc.y += n0 * v0.y + n1 * v1.y + n2 * v2.y + n3 * v3.y;
            acc.z += n0 * v0.z + n1 * v1.z + n2 * v2.z + n3 * v3.z;
            acc.w += n0 * v0.w + n1 * v1.w + n2 * v2.w + n3 * v3.w;
        }
    }
    for (; j < end; j++) {
        int2 p0 = __ldg(&g_epair[j]);
        if (act) {
            float4 v0 = __ldg(&t4[(size_t)p0.x * C4 + lane]);
            float n0 = __int_as_float(p0.y);
            acc.x += n0 * v0.x; acc.y += n0 * v0.y;
            acc.z += n0 * v0.z; acc.w += n0 * v0.w;
        }
    }

    if (LSM) {
        // row-wise log_softmax across the 16-lane group (width-16 butterfly)
        float m = act ? fmaxf(fmaxf(acc.x, acc.y), fmaxf(acc.z, acc.w)) : -INFINITY;
#pragma unroll
        for (int k = 8; k >= 1; k >>= 1)
            m = fmaxf(m, __shfl_xor_sync(0xffffffffu, m, k, 16));
        float s = act ? (__expf(acc.x - m) + __expf(acc.y - m) +
                         __expf(acc.z - m) + __expf(acc.w - m)) : 0.f;
#pragma unroll
        for (int k = 8; k >= 1; k >>= 1)
            s += __shfl_xor_sync(0xffffffffu, s, k, 16);
        float l = m + logf(s);
        if (act) {
            reinterpret_cast<float4*>(outp)[(size_t)row * C4 + lane] =
                make_float4(acc.x - l, acc.y - l, acc.z - l, acc.w - l);
        }
    } else if (act) {
        reinterpret_cast<float4*>(outp)[(size_t)row * C4 + lane] = acc;
    }
}

// ---------------------------------------------------------------------------
// launcher
// ---------------------------------------------------------------------------
extern "C" void kernel_launch(void* const* d_in, const int* in_sizes, int n_in,
                              void* d_out, int out_size) {
    const float* x  = (const float*)d_in[0];
    const int*   ei = (const int*)d_in[1];
    const float* W1 = (const float*)d_in[2];
    const float* b1 = (const float*)d_in[3];
    const float* Wh = (const float*)d_in[4];
    const float* bh = (const float*)d_in[5];
    const float* W2 = (const float*)d_in[6];
    const float* b2 = (const float*)d_in[7];
    float* out = (float*)d_out;

    int N = in_sizes[0] / IN_C;
    int E = in_sizes[1] / 2;
    const int* src = ei;
    const int* dst = ei + E;

    float *p_tmp, *p_h;
    cudaGetSymbolAddress((void**)&p_tmp, g_tmp);
    cudaGetSymbolAddress((void**)&p_h, g_h);

    const int T = 256;
    int nb_N = (N + T - 1) / T;
    int nb_E = (E + T - 1) / T;
    int nb_G = (N + 127) / 128;   // gemm: 128 rows/block
    int nb_A = (N + 15) / 16;     // aggregate: 16 rows/block

    // ---- normalization + CSR build ----
    zero_deg_kernel<<<nb_N, T>>>(N);
    deg_kernel<<<nb_E, T>>>(dst, E);
    scan_block_kernel<<<SCAN_NB, SCAN_BS>>>(N);   // also computes dinv
    scan_bsum_kernel<<<1, SCAN_BS>>>(SCAN_NB);
    add_off_kernel<<<nb_N, T>>>(N, E);
    fill_kernel<<<nb_E, T>>>(src, dst, E);

    // ---- layer 1 ----
    gemm_kernel<IN_C, HID_C, false><<<nb_G, T>>>(x, W1, p_tmp, N);
    aggregate_kernel<HID_C / 4, false><<<nb_A, T>>>(p_tmp, b1, p_h, N);

    // ---- layer 2 ----
    gemm_kernel<HID_C, HID_C, true><<<nb_G, T>>>(p_h, Wh, p_tmp, N);
    aggregate_kernel<HID_C / 4, false><<<nb_A, T>>>(p_tmp, bh, p_h, N);

    // ---- layer 3 (40-wide) + fused log_softmax ----
    gemm_kernel<HID_C, OUT_C, true><<<nb_G, T>>>(p_h, W2, p_tmp, N);
    aggregate_kernel<OUT_C / 4, true><<<nb_A, T>>>(p_tmp, b2, out, N);
}

// round 5
// speedup vs baseline: 2.2780x; 1.0511x over previous
#include <cuda_runtime.h>
#include <cuda_bf16.h>
#include <math.h>

#define N_NODES 100000
#define N_EDGES 1600000
#define IN_C 64
#define HID_C 64
#define OUT_C 40
#define SCAN_BS 512
#define SCAN_NB ((N_NODES + SCAN_BS - 1) / SCAN_BS)   // 196

// Scratch (allocation-free rule: __device__ globals)
__device__ float g_tmp[(size_t)N_NODES * HID_C];   // GEMM output (pre-norm messages)
__device__ float g_h[(size_t)N_NODES * HID_C];     // aggregated layer output / next input
__device__ float g_dinv[N_NODES];
__device__ int   g_deg[N_NODES];
__device__ int   g_rowptr[N_NODES + 1];
__device__ int   g_cursor[N_NODES];
__device__ int   g_bsum[SCAN_NB];
__device__ int   g_boff[SCAN_NB];
__device__ int2  g_epair[N_EDGES];                 // {src, norm(bits)} binned by dst

// ---------------------------------------------------------------------------
// packed f32x2 helpers (Blackwell: 1 instr = 2 fp32 MACs)
// ---------------------------------------------------------------------------
__device__ __forceinline__ void fma2(unsigned long long& d, unsigned long long a,
                                     unsigned long long b) {
    asm("fma.rn.f32x2 %0, %1, %2, %0;" : "+l"(d) : "l"(a), "l"(b));
}
__device__ __forceinline__ unsigned long long bcast2(float x) {
    unsigned long long p;
    asm("mov.b64 %0, {%1, %1};" : "=l"(p) : "f"(x));
    return p;
}
__device__ __forceinline__ unsigned long long pair2(float lo, float hi) {
    unsigned long long p;
    asm("mov.b64 %0, {%1, %2};" : "=l"(p) : "f"(lo), "f"(hi));
    return p;
}
__device__ __forceinline__ void unpack2(unsigned long long p, float& lo, float& hi) {
    asm("mov.b64 {%0, %1}, %2;" : "=f"(lo), "=f"(hi) : "l"(p));
}

// ---------------------------------------------------------------------------
// degree
// ---------------------------------------------------------------------------
__global__ void deg_kernel(const int* __restrict__ dst, int E) {
    int i = blockIdx.x * blockDim.x + threadIdx.x;
    if (i < E) atomicAdd(&g_deg[dst[i]], 1);
}

// ---------------------------------------------------------------------------
// CSR build: block-wise exclusive scan of deg -> rowptr (dinv fused here)
// ---------------------------------------------------------------------------
__global__ void scan_block_kernel(int N) {
    __shared__ int s[SCAN_BS];
    int i = blockIdx.x * SCAN_BS + threadIdx.x;
    int v = (i < N) ? g_deg[i] : 0;
    if (i < N) g_dinv[i] = rsqrtf((float)(v + 1));     // +1 self loop; always > 0
    s[threadIdx.x] = v;
    __syncthreads();
#pragma unroll
    for (int off = 1; off < SCAN_BS; off <<= 1) {
        int t = 0;
        if (threadIdx.x >= off) t = s[threadIdx.x - off];
        __syncthreads();
        if (threadIdx.x >= off) s[threadIdx.x] += t;
        __syncthreads();
    }
    if (i < N) g_rowptr[i] = s[threadIdx.x] - v;       // exclusive, block-local
    if (threadIdx.x == SCAN_BS - 1) g_bsum[blockIdx.x] = s[SCAN_BS - 1];
}

__global__ void scan_bsum_kernel(int NB) {
    __shared__ int s[SCAN_BS];
    int v = (threadIdx.x < NB) ? g_bsum[threadIdx.x] : 0;
    s[threadIdx.x] = v;
    __syncthreads();
#pragma unroll
    for (int off = 1; off < SCAN_BS; off <<= 1) {
        int t = 0;
        if (threadIdx.x >= off) t = s[threadIdx.x - off];
        __syncthreads();
        if (threadIdx.x >= off) s[threadIdx.x] += t;
        __syncthreads();
    }
    if (threadIdx.x < NB) g_boff[threadIdx.x] = s[threadIdx.x] - v;  // exclusive
}

__global__ void add_off_kernel(int N, int E) {
    int i = blockIdx.x * blockDim.x + threadIdx.x;
    if (i < N) {
        int r = g_rowptr[i] + g_boff[i >> 9];
        g_rowptr[i] = r;
        g_cursor[i] = r;
    }
    if (i == 0) g_rowptr[N] = E;
}

__global__ void fill_kernel(const int* __restrict__ src, const int* __restrict__ dst, int E) {
    int e = blockIdx.x * blockDim.x + threadIdx.x;
    if (e >= E) return;
    int s = src[e], d = dst[e];
    float nrm = g_dinv[s] * g_dinv[d];
    int pos = atomicAdd(&g_cursor[d], 1);
    g_epair[pos] = make_int2(s, __float_as_int(nrm));
}

// ---------------------------------------------------------------------------
// dense transform v3: Y[r,:] = (relu?)X[r,:] @ W
// 2 threads per row, interleaved float4 column chunks, f32x2 packed FMA
// (same memory pattern as v2; FMA instruction count halved)
// ---------------------------------------------------------------------------
template <int IN, int OUT, bool RELU>
__global__ void __launch_bounds__(256) gemm_kernel(const float* __restrict__ X,
                                                   const float* __restrict__ W,
                                                   float* __restrict__ Y, int N) {
    constexpr int NJ = OUT / 8;   // float4 chunks per thread (8 for 64, 5 for 40)
    __shared__ __align__(16) float Ws[IN * OUT];
    for (int i = threadIdx.x; i < IN * OUT; i += blockDim.x) Ws[i] = W[i];
    __syncthreads();

    int half = threadIdx.x & 1;
    int r = blockIdx.x * 128 + (threadIdx.x >> 1);
    if (r >= N) return;

    unsigned long long acc[2 * NJ];
#pragma unroll
    for (int j = 0; j < 2 * NJ; j++) acc[j] = 0ull;

    const float4* xr = reinterpret_cast<const float4*>(X + (size_t)r * IN);
#pragma unroll 4
    for (int k4 = 0; k4 < IN / 4; k4++) {
        float4 xv = xr[k4];
        if (RELU) {
            xv.x = fmaxf(xv.x, 0.f); xv.y = fmaxf(xv.y, 0.f);
            xv.z = fmaxf(xv.z, 0.f); xv.w = fmaxf(xv.w, 0.f);
        }
        float xs[4] = {xv.x, xv.y, xv.z, xv.w};
#pragma unroll
        for (int kk = 0; kk < 4; kk++) {
            unsigned long long xx = bcast2(xs[kk]);
            const float4* wr = reinterpret_cast<const float4*>(Ws + (4 * k4 + kk) * OUT);
#pragma unroll
            for (int j = 0; j < NJ; j++) {
                float4 w = wr[2 * j + half];
                fma2(acc[2 * j],     xx, pair2(w.x, w.y));
                fma2(acc[2 * j + 1], xx, pair2(w.z, w.w));
            }
        }
    }
    float4* yr = reinterpret_cast<float4*>(Y + (size_t)r * OUT);
#pragma unroll
    for (int j = 0; j < NJ; j++) {
        float4 o;
        unpack2(acc[2 * j],     o.x, o.y);
        unpack2(acc[2 * j + 1], o.z, o.w);
        yr[2 * j + half] = o;
    }
}

// ---------------------------------------------------------------------------
// CSR aggregate (+ fused self-loop/bias init, optional fused log_softmax):
//   out[d,:] = b + dinv[d]^2 * tmp[d,:] + sum_{e in row d} norm[e] * tmp[src[e],:]
// 16 lanes per row, one float4 per lane; 4-way edge unroll for MLP
// ---------------------------------------------------------------------------
template <int C4, bool LSM>
__global__ void aggregate_kernel(const float* __restrict__ tmp, const float* __restrict__ b,
                                 float* __restrict__ outp, int N) {
    int g    = blockIdx.x * 16 + (threadIdx.x >> 4);
    int lane = threadIdx.x & 15;
    bool rowok = (g < N);
    int row  = rowok ? g : 0;
    bool act = rowok && (lane < C4);

    const float4* t4 = reinterpret_cast<const float4*>(tmp);
    const float4* b4 = reinterpret_cast<const float4*>(b);

    float4 acc = make_float4(0.f, 0.f, 0.f, 0.f);
    int beg = 0, end = 0;
    if (rowok) {
        beg = g_rowptr[row];
        end = g_rowptr[row + 1];
    }
    if (act) {
        float di = g_dinv[row];
        float s2 = di * di;
        float4 t = t4[(size_t)row * C4 + lane];
        float4 bb = b4[lane];
        acc.x = bb.x + s2 * t.x; acc.y = bb.y + s2 * t.y;
        acc.z = bb.z + s2 * t.z; acc.w = bb.w + s2 * t.w;
    }

    int j = beg;
    for (; j + 3 < end; j += 4) {                       // 4-way unroll for MLP
        int2 p0 = __ldg(&g_epair[j]);
        int2 p1 = __ldg(&g_epair[j + 1]);
        int2 p2 = __ldg(&g_epair[j + 2]);
        int2 p3 = __ldg(&g_epair[j + 3]);
        if (act) {
            float4 v0 = __ldg(&t4[(size_t)p0.x * C4 + lane]);
            float4 v1 = __ldg(&t4[(size_t)p1.x * C4 + lane]);
            float4 v2 = __ldg(&t4[(size_t)p2.x * C4 + lane]);
            float4 v3 = __ldg(&t4[(size_t)p3.x * C4 + lane]);
            float n0 = __int_as_float(p0.y), n1 = __int_as_float(p1.y);
            float n2 = __int_as_float(p2.y), n3 = __int_as_float(p3.y);
            acc.x += n0 * v0.x + n1 * v1.x + n2 * v2.x + n3 * v3.x;
            acc.y += n0 * v0.y + n1 * v1.y + n2 * v2.y + n3 * v3.y;
            acc.z += n0 * v0.z + n1 * v1.z + n2 * v2.z + n3 * v3.z;
            acc.w += n0 * v0.w + n1 * v1.w + n2 * v2.w + n3 * v3.w;
        }
    }
    for (; j < end; j++) {
        int2 p0 = __ldg(&g_epair[j]);
        if (act) {
            float4 v0 = __ldg(&t4[(size_t)p0.x * C4 + lane]);
            float n0 = __int_as_float(p0.y);
            acc.x += n0 * v0.x; acc.y += n0 * v0.y;
            acc.z += n0 * v0.z; acc.w += n0 * v0.w;
        }
    }

    if (LSM) {
        // row-wise log_softmax across the 16-lane group (width-16 butterfly)
        float m = act ? fmaxf(fmaxf(acc.x, acc.y), fmaxf(acc.z, acc.w)) : -INFINITY;
#pragma unroll
        for (int k = 8; k >= 1; k >>= 1)
            m = fmaxf(m, __shfl_xor_sync(0xffffffffu, m, k, 16));
        float s = act ? (__expf(acc.x - m) + __expf(acc.y - m) +
                         __expf(acc.z - m) + __expf(acc.w - m)) : 0.f;
#pragma unroll
        for (int k = 8; k >= 1; k >>= 1)
            s += __shfl_xor_sync(0xffffffffu, s, k, 16);
        float l = m + logf(s);
        if (act) {
            reinterpret_cast<float4*>(outp)[(size_t)row * C4 + lane] =
                make_float4(acc.x - l, acc.y - l, acc.z - l, acc.w - l);
        }
    } else if (act) {
        reinterpret_cast<float4*>(outp)[(size_t)row * C4 + lane] = acc;
    }
}

// ---------------------------------------------------------------------------
// launcher: CSR build on default stream, layer-1 GEMM forked onto s2
// ---------------------------------------------------------------------------
extern "C" void kernel_launch(void* const* d_in, const int* in_sizes, int n_in,
                              void* d_out, int out_size) {
    const float* x  = (const float*)d_in[0];
    const int*   ei = (const int*)d_in[1];
    const float* W1 = (const float*)d_in[2];
    const float* b1 = (const float*)d_in[3];
    const float* Wh = (const float*)d_in[4];
    const float* bh = (const float*)d_in[5];
    const float* W2 = (const float*)d_in[6];
    const float* b2 = (const float*)d_in[7];
    float* out = (float*)d_out;

    int N = in_sizes[0] / IN_C;
    int E = in_sizes[1] / 2;
    const int* src = ei;
    const int* dst = ei + E;

    float *p_tmp, *p_h;
    int* p_deg;
    cudaGetSymbolAddress((void**)&p_tmp, g_tmp);
    cudaGetSymbolAddress((void**)&p_h, g_h);
    cudaGetSymbolAddress((void**)&p_deg, g_deg);

    // lazily-created side stream + events (created on the eager correctness
    // call, reused unchanged during graph capture)
    static cudaStream_t s2 = nullptr;
    static cudaEvent_t evFork = nullptr, evJoin = nullptr;
    if (!s2) {
        cudaStreamCreateWithFlags(&s2, cudaStreamNonBlocking);
        cudaEventCreateWithFlags(&evFork, cudaEventDisableTiming);
        cudaEventCreateWithFlags(&evJoin, cudaEventDisableTiming);
    }

    const int T = 256;
    int nb_N = (N + T - 1) / T;
    int nb_E = (E + T - 1) / T;
    int nb_G = (N + 127) / 128;   // gemm: 128 rows/block
    int nb_A = (N + 15) / 16;     // aggregate: 16 rows/block

    // ---- fork: layer-1 GEMM on s2 (independent of CSR build) ----
    cudaEventRecord(evFork, 0);
    cudaStreamWaitEvent(s2, evFork, 0);
    gemm_kernel<IN_C, HID_C, false><<<nb_G, T, 0, s2>>>(x, W1, p_tmp, N);
    cudaEventRecord(evJoin, s2);

    // ---- CSR build on default stream ----
    cudaMemsetAsync(p_deg, 0, (size_t)N * sizeof(int), 0);
    deg_kernel<<<nb_E, T>>>(dst, E);
    scan_block_kernel<<<SCAN_NB, SCAN_BS>>>(N);   // also computes dinv
    scan_bsum_kernel<<<1, SCAN_BS>>>(SCAN_NB);
    add_off_kernel<<<nb_N, T>>>(N, E);
    fill_kernel<<<nb_E, T>>>(src, dst, E);

    // ---- join, then aggregate layer 1 ----
    cudaStreamWaitEvent(0, evJoin, 0);
    aggregate_kernel<HID_C / 4, false><<<nb_A, T>>>(p_tmp, b1, p_h, N);

    // ---- layer 2 ----
    gemm_kernel<HID_C, HID_C, true><<<nb_G, T>>>(p_h, Wh, p_tmp, N);
    aggregate_kernel<HID_C / 4, false><<<nb_A, T>>>(p_tmp, bh, p_h, N);

    // ---- layer 3 (40-wide) + fused log_softmax ----
    gemm_kernel<HID_C, OUT_C, true><<<nb_G, T>>>(p_h, W2, p_tmp, N);
    aggregate_kernel<OUT_C / 4, true><<<nb_A, T>>>(p_tmp, b2, out, N);
}